// round 1
// baseline (speedup 1.0000x reference)
#include <cuda_runtime.h>
#include <cstdint>

// Problem shape (fixed by the dataset)
#define Bv  4
#define Cv  64
#define Hv  384
#define Wv  768
#define HWv (Hv * Wv)          // 294912

// Weight accumulator scratch (device global: no allocations allowed)
__device__ float g_wsum[Bv * HWv];

__device__ __forceinline__ void red_add_f32(float* p, float v) {
    // no-return global reduction: cheaper than atomicAdd (no return path)
    asm volatile("red.global.add.f32 [%0], %1;" :: "l"(p), "f"(v) : "memory");
}

// ---------------------------------------------------------------------------
// Zero the per-pixel weight accumulator (float4 stores)
// ---------------------------------------------------------------------------
__global__ __launch_bounds__(256) void zero_wsum_kernel() {
    int i = blockIdx.x * 256 + threadIdx.x;           // over Bv*HWv/4
    reinterpret_cast<float4*>(g_wsum)[i] = make_float4(0.f, 0.f, 0.f, 0.f);
}

// ---------------------------------------------------------------------------
// Scatter: one thread per source pixel. Coalesced fmap1 reads per channel,
// 65 no-return reductions per valid pixel.
// ---------------------------------------------------------------------------
__global__ __launch_bounds__(256) void scatter_kernel(
    const float* __restrict__ fmap,
    const float* __restrict__ flow,
    const float* __restrict__ depth,
    float* __restrict__ out_feat)
{
    int t = blockIdx.x * 256 + threadIdx.x;           // over Bv*HWv
    int b = t / HWv;
    int p = t - b * HWv;
    int y = p / Wv;
    int x = p - y * Wv;

    float fx = flow[(size_t)(b * 2 + 0) * HWv + p];
    float fy = flow[(size_t)(b * 2 + 1) * HWv + p];
    float tx = (float)x + fx;
    float ty = (float)y + fy;

    // reference: valid = (tx>=0)&(tx<W-1)&(ty>=0)&(ty<H-1)
    if (!(tx >= 0.f && tx < (float)(Wv - 1) && ty >= 0.f && ty < (float)(Hv - 1)))
        return;

    int ix = (int)tx;   // trunc == floor for tx >= 0
    int iy = (int)ty;
    int idx = iy * Wv + ix;

    float w = __expf(-depth[(size_t)b * HWv + p]);

    red_add_f32(&g_wsum[b * HWv + idx], w);

    const float* src = fmap     + (size_t)b * Cv * HWv + p;
    float*       dst = out_feat + (size_t)b * Cv * HWv + idx;

    #pragma unroll 8
    for (int c = 0; c < Cv; c++) {
        float v = src[(size_t)c * HWv] * w;   // coalesced load across warp
        red_add_f32(dst + (size_t)c * HWv, v);
    }
}

// ---------------------------------------------------------------------------
// Normalize in place + write mask (fused into the c==0 slice of the grid).
// Untouched pixels (w==0) hold exact 0.0f from the memset; inv=1 keeps them.
// ---------------------------------------------------------------------------
__global__ __launch_bounds__(256) void normalize_kernel(
    float* __restrict__ out_feat,
    float* __restrict__ out_mask)
{
    int p4 = blockIdx.x * 256 + threadIdx.x;          // float4 index in plane
    int c  = blockIdx.y;
    int b  = blockIdx.z;

    float4 w4 = reinterpret_cast<const float4*>(g_wsum)[b * (HWv / 4) + p4];

    float4 inv;
    inv.x = (w4.x > 0.f) ? (1.f / w4.x) : 1.f;
    inv.y = (w4.y > 0.f) ? (1.f / w4.y) : 1.f;
    inv.z = (w4.z > 0.f) ? (1.f / w4.z) : 1.f;
    inv.w = (w4.w > 0.f) ? (1.f / w4.w) : 1.f;

    size_t o = (size_t)(b * Cv + c) * (HWv / 4) + p4;
    float4 v = reinterpret_cast<float4*>(out_feat)[o];
    v.x *= inv.x; v.y *= inv.y; v.z *= inv.z; v.w *= inv.w;
    reinterpret_cast<float4*>(out_feat)[o] = v;

    if (c == 0) {
        float4 m;
        m.x = (w4.x > 0.f) ? 1.f : 0.f;
        m.y = (w4.y > 0.f) ? 1.f : 0.f;
        m.z = (w4.z > 0.f) ? 1.f : 0.f;
        m.w = (w4.w > 0.f) ? 1.f : 0.f;
        reinterpret_cast<float4*>(out_mask)[b * (HWv / 4) + p4] = m;
    }
}

// ---------------------------------------------------------------------------
// Launch
// ---------------------------------------------------------------------------
extern "C" void kernel_launch(void* const* d_in, const int* in_sizes, int n_in,
                              void* d_out, int out_size)
{
    const float* fmap  = (const float*)d_in[0];  // (B, C, H, W)
    const float* flow  = (const float*)d_in[1];  // (B, 2, H, W)
    const float* depth = (const float*)d_in[2];  // (B, 1, H, W)

    float* out_feat = (float*)d_out;                               // (B,C,H,W)
    float* out_mask = out_feat + (size_t)Bv * Cv * HWv;            // (B,1,H,W)

    // Zero the feature accumulation region (we scatter straight into d_out)
    cudaMemsetAsync(out_feat, 0, (size_t)Bv * Cv * HWv * sizeof(float));

    zero_wsum_kernel<<<(Bv * HWv) / 1024, 256>>>();

    scatter_kernel<<<(Bv * HWv) / 256, 256>>>(fmap, flow, depth, out_feat);

    dim3 grid(HWv / 1024, Cv, Bv);   // 288 x 64 x 4
    normalize_kernel<<<grid, 256>>>(out_feat, out_mask);
}

// round 2
// speedup vs baseline: 1.8636x; 1.8636x over previous
#include <cuda_runtime.h>
#include <cstdint>

// Problem shape (fixed by the dataset)
#define Bv  4
#define Cv  64
#define Hv  384
#define Wv  768
#define HWv (Hv * Wv)          // 294912

// Channel-contiguous accumulator: (B, HW, C). 302 MB device-global scratch
// (allocations are forbidden; module-scope arrays are the sanctioned path).
__device__ __align__(256) float g_scratch[(size_t)Bv * HWv * Cv];
__device__ __align__(256) float g_wsum[Bv * HWv];

__device__ __forceinline__ void red_add_f32(float* p, float v) {
    asm volatile("red.global.add.f32 [%0], %1;" :: "l"(p), "f"(v) : "memory");
}

__device__ __forceinline__ void red_add_v4(float* p, float a, float b, float c, float d) {
    asm volatile("red.global.add.v4.f32 [%0], {%1, %2, %3, %4};"
                 :: "l"(p), "f"(a), "f"(b), "f"(c), "f"(d) : "memory");
}

// ---------------------------------------------------------------------------
// Scatter: one thread per source pixel. 64 coalesced fmap loads,
// 16 vector reductions + 1 scalar weight reduction per valid pixel.
// ---------------------------------------------------------------------------
__global__ __launch_bounds__(256) void scatter_kernel(
    const float* __restrict__ fmap,
    const float* __restrict__ flow,
    const float* __restrict__ depth)
{
    int t = blockIdx.x * 256 + threadIdx.x;           // over Bv*HWv
    int b = t / HWv;
    int p = t - b * HWv;
    int y = p / Wv;
    int x = p - y * Wv;

    float fx = flow[(size_t)(b * 2 + 0) * HWv + p];
    float fy = flow[(size_t)(b * 2 + 1) * HWv + p];
    float tx = (float)x + fx;
    float ty = (float)y + fy;

    // reference: valid = (tx>=0)&(tx<W-1)&(ty>=0)&(ty<H-1)
    if (!(tx >= 0.f && tx < (float)(Wv - 1) && ty >= 0.f && ty < (float)(Hv - 1)))
        return;

    int ix = (int)tx;   // trunc == floor for tx >= 0
    int iy = (int)ty;
    int idx = iy * Wv + ix;

    float w = __expf(-depth[(size_t)b * HWv + p]);

    red_add_f32(&g_wsum[b * HWv + idx], w);

    const float* src = fmap + (size_t)b * Cv * HWv + p;           // stride HWv over c
    float*       dst = g_scratch + ((size_t)b * HWv + idx) * Cv;  // contiguous over c

    #pragma unroll
    for (int c = 0; c < Cv; c += 4) {
        float v0 = src[(size_t)(c + 0) * HWv] * w;
        float v1 = src[(size_t)(c + 1) * HWv] * w;
        float v2 = src[(size_t)(c + 2) * HWv] * w;
        float v3 = src[(size_t)(c + 3) * HWv] * w;
        red_add_v4(dst + c, v0, v1, v2, v3);
    }
}

// ---------------------------------------------------------------------------
// Transpose (B,HW,C) -> (B,C,HW) through padded smem tile, fused with
// weight normalization + mask write. Untouched pixels: scratch==0, so
// output is exact 0 regardless of inv.
// ---------------------------------------------------------------------------
__global__ __launch_bounds__(256) void transpose_norm_kernel(
    float* __restrict__ out_feat,
    float* __restrict__ out_mask)
{
    __shared__ float tile[32][Cv + 1];   // +1 pad: conflict-free column reads
    __shared__ float s_inv[32];
    __shared__ float s_msk[32];

    int tid = threadIdx.x;
    int p0  = blockIdx.x * 32;           // 32 pixels per block
    int b   = blockIdx.y;

    // Load 32 pixels x 64 channels as float4 (coalesced: 16 float4 per pixel row)
    const float4* src4 = reinterpret_cast<const float4*>(g_scratch)
                       + ((size_t)b * HWv + p0) * (Cv / 4);
    #pragma unroll
    for (int i = 0; i < 2; i++) {
        int e   = tid + i * 256;         // 0..511
        int pix = e >> 4;                // /16
        int c4  = e & 15;
        float4 v = src4[pix * (Cv / 4) + c4];
        tile[pix][c4 * 4 + 0] = v.x;
        tile[pix][c4 * 4 + 1] = v.y;
        tile[pix][c4 * 4 + 2] = v.z;
        tile[pix][c4 * 4 + 3] = v.w;
    }
    if (tid < 32) {
        float w = g_wsum[(size_t)b * HWv + p0 + tid];
        s_inv[tid] = (w > 0.f) ? (1.f / w) : 1.f;
        s_msk[tid] = (w > 0.f) ? 1.f : 0.f;
    }
    __syncthreads();

    // Write: lane -> pixel (coalesced per channel), 8 channels per thread
    int lane = tid & 31;
    int cb   = tid >> 5;                 // 0..7
    float inv = s_inv[lane];
    #pragma unroll
    for (int c = cb; c < Cv; c += 8) {
        out_feat[((size_t)b * Cv + c) * HWv + p0 + lane] = tile[lane][c] * inv;
    }
    if (tid < 32) {
        out_mask[(size_t)b * HWv + p0 + tid] = s_msk[tid];
    }
}

// ---------------------------------------------------------------------------
// Launch
// ---------------------------------------------------------------------------
extern "C" void kernel_launch(void* const* d_in, const int* in_sizes, int n_in,
                              void* d_out, int out_size)
{
    const float* fmap  = (const float*)d_in[0];  // (B, C, H, W)
    const float* flow  = (const float*)d_in[1];  // (B, 2, H, W)
    const float* depth = (const float*)d_in[2];  // (B, 1, H, W)

    float* out_feat = (float*)d_out;                               // (B,C,H,W)
    float* out_mask = out_feat + (size_t)Bv * Cv * HWv;            // (B,1,H,W)

    void* scratch_ptr = nullptr;
    void* wsum_ptr    = nullptr;
    cudaGetSymbolAddress(&scratch_ptr, g_scratch);
    cudaGetSymbolAddress(&wsum_ptr,    g_wsum);

    cudaMemsetAsync(scratch_ptr, 0, (size_t)Bv * HWv * Cv * sizeof(float));
    cudaMemsetAsync(wsum_ptr,    0, (size_t)Bv * HWv * sizeof(float));

    scatter_kernel<<<(Bv * HWv) / 256, 256>>>(fmap, flow, depth);

    dim3 grid(HWv / 32, Bv);             // 9216 x 4
    transpose_norm_kernel<<<grid, 256>>>(out_feat, out_mask);
}